// round 13
// baseline (speedup 1.0000x reference)
#include <cuda_runtime.h>
#include <math.h>
#include <stdint.h>

// NoisyTopkRouter — TF32x3 split-fp32 via mma.sync.
// R12: convoy-breaking. Two independent 256-thread half-pipelines per CTA:
// each half owns 64 tokens, its own X ring + W ring + cp.async groups + named
// barrier. Halves phase-drift so one half's MMAs cover the other's load/barrier
// phases. Per-warp compute body identical to R10.
//
// C[32768 x 128] = X[32768 x 2048] * W^T (W rows 0..63 route, 64..127 noise)
// Epilogue: noisy = logits + eps*softplus(noise); top-2; 2-way softmax scatter.

#define MT      128
#define THREADS 512
#define SROW    36                         // floats per X smem row
#define XSTG    (64 * SROW * 4)            // X stage per half = 9216 B
#define WSLAB   512
#define WTILE   16384
#define WKTB    (2 * WTILE)                // 32768 B per W k-tile
#define WB0     (4 * XSTG)                 // W region base (36864)
#define SMEMB   (WB0 + 4 * WKTB)           // 36864 + 131072 = 167936 B
#define NKT     64
#define PADC    130

__device__ unsigned char g_Wpre[NKT * WKTB];   // pre-split W, fragment order

static __device__ __forceinline__ uint32_t f2tf32(float x) {
    uint32_t r;
    asm("cvt.rna.tf32.f32 %0, %1;" : "=r"(r) : "f"(x));
    return r;
}
static __device__ __forceinline__ void split2(float a, uint32_t& hi, uint32_t& lo) {
    hi = f2tf32(a);
    lo = f2tf32(a - __uint_as_float(hi));
}

static __device__ __forceinline__ void mma_tf32(float* d,
                                                uint32_t a0, uint32_t a1,
                                                uint32_t a2, uint32_t a3,
                                                uint32_t b0, uint32_t b1) {
    asm volatile(
        "mma.sync.aligned.m16n8k8.row.col.f32.tf32.tf32.f32 "
        "{%0,%1,%2,%3}, {%4,%5,%6,%7}, {%8,%9}, {%0,%1,%2,%3};"
        : "+f"(d[0]), "+f"(d[1]), "+f"(d[2]), "+f"(d[3])
        : "r"(a0), "r"(a1), "r"(a2), "r"(a3), "r"(b0), "r"(b1));
}

static __device__ __forceinline__ void cp16(uint32_t saddr, const void* gaddr) {
    asm volatile("cp.async.ca.shared.global [%0], [%1], 16;"
                 :: "r"(saddr), "l"(gaddr));
}
static __device__ __forceinline__ uint4 lds128(uint32_t a) {
    uint4 v;
    asm volatile("ld.shared.v4.u32 {%0,%1,%2,%3}, [%4];"
                 : "=r"(v.x), "=r"(v.y), "=r"(v.z), "=r"(v.w) : "r"(a));
    return v;
}
static __device__ __forceinline__ void bar_half(int id) {
    asm volatile("bar.sync %0, 256;" :: "r"(id) : "memory");
}

// ---------------- pre-kernel: split W into fragment-ordered slabs ----------
__global__ void presplit_w(const float* __restrict__ Wr,
                           const float* __restrict__ Wn, int D)
{
    const int kt = blockIdx.x;
    for (int idx = threadIdx.x; idx < 4096; idx += 256) {
        const int n  = idx >> 5;
        const int kc = idx & 31;
        const int k  = kt * 32 + kc;
        const float w = (n < 64) ? Wr[(size_t)n * D + k]
                                 : Wn[(size_t)(n - 64) * D + k];
        const uint32_t hi = f2tf32(w);
        const uint32_t lo = f2tf32(w - __uint_as_float(hi));
        const int slab = (n >> 5) * 8 + ((n >> 4) & 1) * 4 + (kc >> 3);
        const int ln   = (n & 7) * 4 + (kc & 3);
        const int r    = ((n >> 3) & 1) * 2 + ((kc >> 2) & 1);
        const int off  = slab * WSLAB + ln * 16 + r * 4;
        *(uint32_t*)(g_Wpre + (size_t)kt * WKTB + off)         = hi;
        *(uint32_t*)(g_Wpre + (size_t)kt * WKTB + WTILE + off) = lo;
    }
}

// ---------------- main kernel ---------------------------------------------
__global__ __launch_bounds__(THREADS, 1)
void noisy_topk_router_mma(const float* __restrict__ x,
                           const float* __restrict__ br,
                           const float* __restrict__ bn,
                           const float* __restrict__ eps,
                           float* __restrict__ out,
                           int Ntok, int D, long long out_size)
{
    extern __shared__ char smem[];
    uint32_t smem_u;
    asm("{ .reg .u64 t; cvta.to.shared.u64 t, %1; cvt.u32.u64 %0, t; }"
        : "=r"(smem_u) : "l"(smem));

    const int tid  = threadIdx.x;
    const int h    = tid >> 8;        // half id (0,1)
    const int htid = tid & 255;
    const int hwid = htid >> 5;       // 0..7
    const int lane = tid & 31;
    const int gid  = lane >> 2;
    const int tig  = lane & 3;
    const int wm   = hwid & 1;        // warp m-row within half (2 x 32 tokens)
    const int wn   = hwid >> 1;       // warp n-col (4 x 32 outputs)
    const int m0   = blockIdx.x * MT;

    // half-private smem bases
    const uint32_t xbase = smem_u + (uint32_t)(h * 2 * XSTG);
    const uint32_t wbase = smem_u + WB0 + (uint32_t)(h * 2 * WKTB);

    // X producer: 2 cp16/thread/stage (prow 0..63 within half)
    const int prow = htid >> 2;
    const int pqf  = (htid & 3) * 4;
    const float* xsrc = &x[(size_t)(m0 + h * 64 + prow) * D + pqf];
    const uint32_t pdst = xbase + prow * (SROW * 4) + pqf * 4;

    // W producer: 8 cp16/thread/stage (linear copy of 32KB by 256 threads)
    const uint32_t wdst0 = wbase + htid * 16;

    // consumer bases
    const uint32_t aoff = (uint32_t)((wm * 32 + gid) * SROW + tig) * 4;
    const uint32_t wfb  = wbase + (uint32_t)(wn * 8) * WSLAB + lane * 16;

    float acc[2][4][4];
#pragma unroll
    for (int f = 0; f < 2; ++f)
#pragma unroll
        for (int g = 0; g < 4; ++g)
#pragma unroll
            for (int i = 0; i < 4; ++i) acc[f][g][i] = 0.0f;

    const int nTiles = D / 32;        // 64

    // ---- prologue: stages 0,1 in flight (per half) ----
#pragma unroll
    for (int s = 0; s < 2; ++s) {
        cp16(pdst + s * XSTG, xsrc + s * 32);
        cp16(pdst + s * XSTG + 64, xsrc + s * 32 + 16);
        const unsigned char* wsrc = g_Wpre + (size_t)s * WKTB + htid * 16;
#pragma unroll
        for (int q = 0; q < 8; ++q)
            cp16(wdst0 + s * WKTB + q * 4096, wsrc + q * 4096);
        asm volatile("cp.async.commit_group;" ::: "memory");
    }

#pragma unroll 1
    for (int kt = 0; kt < nTiles; ++kt) {
        const int b = kt & 1;

        asm volatile("cp.async.wait_group 1;" ::: "memory");
        bar_half(h + 1);

        const uint32_t aB  = xbase + (uint32_t)(b * XSTG) + aoff;
        const uint32_t wst = wfb + (uint32_t)(b * WKTB);

#pragma unroll
        for (int kcq = 0; kcq < 4; ++kcq) {
            const uint4 Bh0 = lds128(wst + kcq * WSLAB);
            const uint4 Bh1 = lds128(wst + (4 + kcq) * WSLAB);
            const uint4 Bl0 = lds128(wst + WTILE + kcq * WSLAB);
            const uint4 Bl1 = lds128(wst + WTILE + (4 + kcq) * WSLAB);

            uint32_t Ah[2][4], Al[2][4];
#pragma unroll
            for (int f = 0; f < 2; ++f) {
                const float* q = reinterpret_cast<const float*>(0) ;
                (void)q;
                const uint32_t qa = aB + (f * 16 * SROW + kcq * 8) * 4;
                float v0, v1, v2, v3;
                asm volatile("ld.shared.f32 %0, [%1];"      : "=f"(v0) : "r"(qa));
                asm volatile("ld.shared.f32 %0, [%1];"      : "=f"(v1) : "r"(qa + 8 * SROW * 4));
                asm volatile("ld.shared.f32 %0, [%1];"      : "=f"(v2) : "r"(qa + 16));
                asm volatile("ld.shared.f32 %0, [%1];"      : "=f"(v3) : "r"(qa + 8 * SROW * 4 + 16));
                split2(v0, Ah[f][0], Al[f][0]);
                split2(v1, Ah[f][1], Al[f][1]);
                split2(v2, Ah[f][2], Al[f][2]);
                split2(v3, Ah[f][3], Al[f][3]);
            }

            // pass hi*hi
#pragma unroll
            for (int f = 0; f < 2; ++f) {
                mma_tf32(acc[f][0], Ah[f][0], Ah[f][1], Ah[f][2], Ah[f][3], Bh0.x, Bh0.y);
                mma_tf32(acc[f][1], Ah[f][0], Ah[f][1], Ah[f][2], Ah[f][3], Bh0.z, Bh0.w);
                mma_tf32(acc[f][2], Ah[f][0], Ah[f][1], Ah[f][2], Ah[f][3], Bh1.x, Bh1.y);
                mma_tf32(acc[f][3], Ah[f][0], Ah[f][1], Ah[f][2], Ah[f][3], Bh1.z, Bh1.w);
            }
            // pass hi*lo
#pragma unroll
            for (int f = 0; f < 2; ++f) {
                mma_tf32(acc[f][0], Ah[f][0], Ah[f][1], Ah[f][2], Ah[f][3], Bl0.x, Bl0.y);
                mma_tf32(acc[f][1], Ah[f][0], Ah[f][1], Ah[f][2], Ah[f][3], Bl0.z, Bl0.w);
                mma_tf32(acc[f][2], Ah[f][0], Ah[f][1], Ah[f][2], Ah[f][3], Bl1.x, Bl1.y);
                mma_tf32(acc[f][3], Ah[f][0], Ah[f][1], Ah[f][2], Ah[f][3], Bl1.z, Bl1.w);
            }
            // pass lo*hi
#pragma unroll
            for (int f = 0; f < 2; ++f) {
                mma_tf32(acc[f][0], Al[f][0], Al[f][1], Al[f][2], Al[f][3], Bh0.x, Bh0.y);
                mma_tf32(acc[f][1], Al[f][0], Al[f][1], Al[f][2], Al[f][3], Bh0.z, Bh0.w);
                mma_tf32(acc[f][2], Al[f][0], Al[f][1], Al[f][2], Al[f][3], Bh1.x, Bh1.y);
                mma_tf32(acc[f][3], Al[f][0], Al[f][1], Al[f][2], Al[f][3], Bh1.z, Bh1.w);
            }
        }
        bar_half(h + 1);     // WAR: all half's warps done reading stage b

        if (kt + 2 < nTiles) {
            cp16(pdst + b * XSTG, xsrc + (kt + 2) * 32);
            cp16(pdst + b * XSTG + 64, xsrc + (kt + 2) * 32 + 16);
            const unsigned char* wsrc = g_Wpre + (size_t)(kt + 2) * WKTB + htid * 16;
#pragma unroll
            for (int q = 0; q < 8; ++q)
                cp16(wdst0 + b * WKTB + q * 4096, wsrc + q * 4096);
        }
        asm volatile("cp.async.commit_group;" ::: "memory");
    }
    __syncthreads();

    // ---- stage accumulators to smem ----
    float* Cs = reinterpret_cast<float*>(smem);
#pragma unroll
    for (int f = 0; f < 2; ++f)
#pragma unroll
        for (int g = 0; g < 4; ++g) {
            const int row = h * 64 + wm * 32 + f * 16 + gid;
            const int col = wn * 32 + g * 8 + 2 * tig;
            *reinterpret_cast<float2*>(&Cs[row * PADC + col]) =
                make_float2(acc[f][g][0], acc[f][g][1]);
            *reinterpret_cast<float2*>(&Cs[(row + 8) * PADC + col]) =
                make_float2(acc[f][g][2], acc[f][g][3]);
        }
    __syncthreads();

    // ---- epilogue: one thread per token ----
    if (tid < MT) {
        const int tok = m0 + tid;
        const float* crow = &Cs[tid * PADC];

        float v1 = -INFINITY, v2 = -INFINITY;
        int   i1 = -1, i2 = -1;
#pragma unroll 8
        for (int e = 0; e < 64; ++e) {
            const float lg = crow[e]      + __ldg(&br[e]);
            const float ns = crow[64 + e] + __ldg(&bn[e]);
            const float sp = fmaxf(ns, 0.0f) + log1pf(expf(-fabsf(ns)));
            const float nv = lg + __ldg(&eps[(size_t)tok * 64 + e]) * sp;
            if (nv > v1)      { v2 = v1; i2 = i1; v1 = nv; i1 = e; }
            else if (nv > v2) { v2 = nv; i2 = e; }
        }

        const float ed = expf(v2 - v1);
        const float s  = 1.0f + ed;
        const float p1 = 1.0f / s;
        const float p2 = ed / s;

        float* orow = out + (size_t)tok * 64;
#pragma unroll
        for (int e4 = 0; e4 < 64; e4 += 4) {
            float vv[4] = {0.0f, 0.0f, 0.0f, 0.0f};
            if (i1 >= e4 && i1 < e4 + 4) vv[i1 - e4] = p1;
            if (i2 >= e4 && i2 < e4 + 4) vv[i2 - e4] = p2;
            *reinterpret_cast<float4*>(orow + e4) =
                make_float4(vv[0], vv[1], vv[2], vv[3]);
        }

        const long long ibase = (long long)Ntok * 64;
        if (out_size >= ibase + (long long)Ntok * 2) {
            out[ibase + (long long)tok * 2 + 0] = (float)i1;
            out[ibase + (long long)tok * 2 + 1] = (float)i2;
        }
    }
}

extern "C" void kernel_launch(void* const* d_in, const int* in_sizes, int n_in,
                              void* d_out, int out_size)
{
    const float* x   = (const float*)d_in[0];
    const float* Wr  = (const float*)d_in[1];
    const float* br  = (const float*)d_in[2];
    const float* Wn  = (const float*)d_in[3];
    const float* bn  = (const float*)d_in[4];
    const float* eps = (const float*)d_in[5];
    float* out = (float*)d_out;
    (void)n_in;

    const int E    = in_sizes[2];              // 64
    const int D    = in_sizes[1] / E;          // 2048
    const int Ntok = in_sizes[0] / D;          // 32768

    static int configured = 0;                 // idempotent attribute set
    if (!configured) {
        cudaFuncSetAttribute(noisy_topk_router_mma,
                             cudaFuncAttributeMaxDynamicSharedMemorySize, SMEMB);
        configured = 1;
    }

    presplit_w<<<D / 32, 256>>>(Wr, Wn, D);
    noisy_topk_router_mma<<<Ntok / MT, THREADS, SMEMB>>>(
        x, br, bn, eps, out, Ntok, D, (long long)out_size);
}

// round 16
// speedup vs baseline: 1.0159x; 1.0159x over previous
#include <cuda_runtime.h>
#include <math.h>
#include <stdint.h>

// NoisyTopkRouter — TF32x3 split-fp32 via mma.sync.
// R13 = R10 structure with doubled warp concurrency: 1024 threads / 32 warps,
// warp tile 16x32 (acc 16 regs -> ~60 regs/thread, fits 32 warps/SM).
// 8 warps/SMSP cover LDS + MMA-RAW latency that 4 could not.
//
// C[32768 x 128] = X[32768 x 2048] * W^T (W rows 0..63 route, 64..127 noise)
// Epilogue: noisy = logits + eps*softplus(noise); top-2; 2-way softmax scatter.

#define MT      128
#define THREADS 1024
#define NSTAGE  3
#define SROW    36                        // floats per X smem row
#define XSTAGE  (128 * SROW * 4)          // 18432 B
#define WSLAB   512                       // W slab stride (bytes)
#define WTILE   16384                     // hi (or lo) W bytes per k-tile
#define WKTB    (2 * WTILE)               // hi+lo = 32768
#define WBASE   (NSTAGE * XSTAGE)         // W ring starts after X ring
#define SMEMB   (WBASE + NSTAGE * WKTB)   // 153600 B
#define NKT     64
#define PADC    130

__device__ unsigned char g_Wpre[NKT * WKTB];   // pre-split W, fragment order

static __device__ __forceinline__ uint32_t f2tf32(float x) {
    uint32_t r;
    asm("cvt.rna.tf32.f32 %0, %1;" : "=r"(r) : "f"(x));
    return r;
}
static __device__ __forceinline__ void split2(float a, uint32_t& hi, uint32_t& lo) {
    hi = f2tf32(a);
    lo = f2tf32(a - __uint_as_float(hi));
}

static __device__ __forceinline__ void mma_tf32(float* d,
                                                uint32_t a0, uint32_t a1,
                                                uint32_t a2, uint32_t a3,
                                                uint32_t b0, uint32_t b1) {
    asm volatile(
        "mma.sync.aligned.m16n8k8.row.col.f32.tf32.tf32.f32 "
        "{%0,%1,%2,%3}, {%4,%5,%6,%7}, {%8,%9}, {%0,%1,%2,%3};"
        : "+f"(d[0]), "+f"(d[1]), "+f"(d[2]), "+f"(d[3])
        : "r"(a0), "r"(a1), "r"(a2), "r"(a3), "r"(b0), "r"(b1));
}

static __device__ __forceinline__ void cp16(uint32_t saddr, const void* gaddr) {
    asm volatile("cp.async.ca.shared.global [%0], [%1], 16;"
                 :: "r"(saddr), "l"(gaddr));
}
static __device__ __forceinline__ uint4 lds128(uint32_t a) {
    uint4 v;
    asm volatile("ld.shared.v4.u32 {%0,%1,%2,%3}, [%4];"
                 : "=r"(v.x), "=r"(v.y), "=r"(v.z), "=r"(v.w) : "r"(a));
    return v;
}

// ---------------- pre-kernel: split W into fragment-ordered slabs ----------
__global__ void presplit_w(const float* __restrict__ Wr,
                           const float* __restrict__ Wn, int D)
{
    const int kt = blockIdx.x;
    for (int idx = threadIdx.x; idx < 4096; idx += 256) {
        const int n  = idx >> 5;
        const int kc = idx & 31;
        const int k  = kt * 32 + kc;
        const float w = (n < 64) ? Wr[(size_t)n * D + k]
                                 : Wn[(size_t)(n - 64) * D + k];
        const uint32_t hi = f2tf32(w);
        const uint32_t lo = f2tf32(w - __uint_as_float(hi));
        const int slab = (n >> 5) * 8 + ((n >> 4) & 1) * 4 + (kc >> 3);
        const int ln   = (n & 7) * 4 + (kc & 3);
        const int r    = ((n >> 3) & 1) * 2 + ((kc >> 2) & 1);
        const int off  = slab * WSLAB + ln * 16 + r * 4;
        *(uint32_t*)(g_Wpre + (size_t)kt * WKTB + off)         = hi;
        *(uint32_t*)(g_Wpre + (size_t)kt * WKTB + WTILE + off) = lo;
    }
}

// ---------------- main kernel ---------------------------------------------
__global__ __launch_bounds__(THREADS, 1)
void noisy_topk_router_mma(const float* __restrict__ x,
                           const float* __restrict__ br,
                           const float* __restrict__ bn,
                           const float* __restrict__ eps,
                           float* __restrict__ out,
                           int Ntok, int D, long long out_size)
{
    extern __shared__ char smem[];
    uint32_t smem_u;
    asm("{ .reg .u64 t; cvta.to.shared.u64 t, %1; cvt.u32.u64 %0, t; }"
        : "=r"(smem_u) : "l"(smem));

    const int tid  = threadIdx.x;
    const int wid  = tid >> 5;      // 0..31
    const int lane = tid & 31;
    const int gid  = lane >> 2;
    const int tig  = lane & 3;
    const int wm   = wid & 7;       // warp m-row (8 x 16 tokens)
    const int wn   = wid >> 3;      // warp n-col (4 x 32 outputs)
    const int m0   = blockIdx.x * MT;

    // X producer: 1 cp16/thread/stage (prow = tid>>3, pqf = (tid&7)*4)
    const int prow = tid >> 3;
    const int pqf  = (tid & 7) * 4;
    const float* xsrc = &x[(size_t)(m0 + prow) * D + pqf];
    const uint32_t pdst = smem_u + prow * (SROW * 4) + pqf * 4;

    // W producer: 2 cp16/thread/stage (linear copy, layout preserved)
    const uint32_t wdst0 = smem_u + WBASE + tid * 16;

    // W consumer fragment base (within a W stage)
    const uint32_t wfb = smem_u + WBASE + (uint32_t)(wn * 8) * WSLAB + lane * 16;

    float acc[4][4];
#pragma unroll
    for (int g = 0; g < 4; ++g)
#pragma unroll
        for (int i = 0; i < 4; ++i) acc[g][i] = 0.0f;

    const int nTiles = D / 32;      // 64

    // ---- prologue: stages 0,1 (X and W) in flight ----
#pragma unroll
    for (int s = 0; s < 2; ++s) {
        cp16(pdst + s * XSTAGE, xsrc + s * 32);
        const unsigned char* wsrc = g_Wpre + (size_t)s * WKTB + tid * 16;
        cp16(wdst0 + s * WKTB, wsrc);
        cp16(wdst0 + s * WKTB + 16384, wsrc + 16384);
        asm volatile("cp.async.commit_group;" ::: "memory");
    }

    int stage = 0;
#pragma unroll 1
    for (int kt = 0; kt < nTiles; ++kt) {
        if (kt + 2 < nTiles) {
            const int s2 = (stage + 2 >= NSTAGE) ? stage + 2 - NSTAGE : stage + 2;
            cp16(pdst + s2 * XSTAGE, xsrc + (kt + 2) * 32);
            const unsigned char* wsrc = g_Wpre + (size_t)(kt + 2) * WKTB + tid * 16;
            cp16(wdst0 + s2 * WKTB, wsrc);
            cp16(wdst0 + s2 * WKTB + 16384, wsrc + 16384);
        }
        asm volatile("cp.async.commit_group;" ::: "memory");
        asm volatile("cp.async.wait_group 2;" ::: "memory");
        __syncthreads();

        const float* Xs = reinterpret_cast<const float*>(smem + stage * XSTAGE);
        const float* aB = Xs + (wm * 16 + gid) * SROW + tig;
        const uint32_t wst = wfb + (uint32_t)(stage * WKTB);

#pragma unroll
        for (int kcq = 0; kcq < 4; ++kcq) {
            // B fragments: 4 conflict-free LDS.128
            const uint4 Bh0 = lds128(wst + kcq * WSLAB);
            const uint4 Bh1 = lds128(wst + (4 + kcq) * WSLAB);
            const uint4 Bl0 = lds128(wst + WTILE + kcq * WSLAB);
            const uint4 Bl1 = lds128(wst + WTILE + (4 + kcq) * WSLAB);

            // A fragments: 4 LDS.32 + split at consume (m16 tile)
            uint32_t Ah[4], Al[4];
            {
                const float* q = aB + kcq * 8;
                split2(q[0],            Ah[0], Al[0]);
                split2(q[8 * SROW],     Ah[1], Al[1]);
                split2(q[4],            Ah[2], Al[2]);
                split2(q[8 * SROW + 4], Ah[3], Al[3]);
            }

            // pass hi*hi
            mma_tf32(acc[0], Ah[0], Ah[1], Ah[2], Ah[3], Bh0.x, Bh0.y);
            mma_tf32(acc[1], Ah[0], Ah[1], Ah[2], Ah[3], Bh0.z, Bh0.w);
            mma_tf32(acc[2], Ah[0], Ah[1], Ah[2], Ah[3], Bh1.x, Bh1.y);
            mma_tf32(acc[3], Ah[0], Ah[1], Ah[2], Ah[3], Bh1.z, Bh1.w);
            // pass hi*lo
            mma_tf32(acc[0], Ah[0], Ah[1], Ah[2], Ah[3], Bl0.x, Bl0.y);
            mma_tf32(acc[1], Ah[0], Ah[1], Ah[2], Ah[3], Bl0.z, Bl0.w);
            mma_tf32(acc[2], Ah[0], Ah[1], Ah[2], Ah[3], Bl1.x, Bl1.y);
            mma_tf32(acc[3], Ah[0], Ah[1], Ah[2], Ah[3], Bl1.z, Bl1.w);
            // pass lo*hi
            mma_tf32(acc[0], Al[0], Al[1], Al[2], Al[3], Bh0.x, Bh0.y);
            mma_tf32(acc[1], Al[0], Al[1], Al[2], Al[3], Bh0.z, Bh0.w);
            mma_tf32(acc[2], Al[0], Al[1], Al[2], Al[3], Bh1.x, Bh1.y);
            mma_tf32(acc[3], Al[0], Al[1], Al[2], Al[3], Bh1.z, Bh1.w);
        }
        __syncthreads();
        stage = (stage + 1 == NSTAGE) ? 0 : stage + 1;
    }

    // ---- stage accumulators to smem ----
    float* Cs = reinterpret_cast<float*>(smem);
#pragma unroll
    for (int g = 0; g < 4; ++g) {
        const int row = wm * 16 + gid;
        const int col = wn * 32 + g * 8 + 2 * tig;
        *reinterpret_cast<float2*>(&Cs[row * PADC + col]) =
            make_float2(acc[g][0], acc[g][1]);
        *reinterpret_cast<float2*>(&Cs[(row + 8) * PADC + col]) =
            make_float2(acc[g][2], acc[g][3]);
    }
    __syncthreads();

    // ---- epilogue: one thread per token ----
    if (tid < MT) {
        const int tok = m0 + tid;
        const float* crow = &Cs[tid * PADC];

        float v1 = -INFINITY, v2 = -INFINITY;
        int   i1 = -1, i2 = -1;
#pragma unroll 8
        for (int e = 0; e < 64; ++e) {
            const float lg = crow[e]      + __ldg(&br[e]);
            const float ns = crow[64 + e] + __ldg(&bn[e]);
            const float sp = fmaxf(ns, 0.0f) + log1pf(expf(-fabsf(ns)));
            const float nv = lg + __ldg(&eps[(size_t)tok * 64 + e]) * sp;
            if (nv > v1)      { v2 = v1; i2 = i1; v1 = nv; i1 = e; }
            else if (nv > v2) { v2 = nv; i2 = e; }
        }

        const float ed = expf(v2 - v1);
        const float s  = 1.0f + ed;
        const float p1 = 1.0f / s;
        const float p2 = ed / s;

        float* orow = out + (size_t)tok * 64;
#pragma unroll
        for (int e4 = 0; e4 < 64; e4 += 4) {
            float vv[4] = {0.0f, 0.0f, 0.0f, 0.0f};
            if (i1 >= e4 && i1 < e4 + 4) vv[i1 - e4] = p1;
            if (i2 >= e4 && i2 < e4 + 4) vv[i2 - e4] = p2;
            *reinterpret_cast<float4*>(orow + e4) =
                make_float4(vv[0], vv[1], vv[2], vv[3]);
        }

        const long long ibase = (long long)Ntok * 64;
        if (out_size >= ibase + (long long)Ntok * 2) {
            out[ibase + (long long)tok * 2 + 0] = (float)i1;
            out[ibase + (long long)tok * 2 + 1] = (float)i2;
        }
    }
}

extern "C" void kernel_launch(void* const* d_in, const int* in_sizes, int n_in,
                              void* d_out, int out_size)
{
    const float* x   = (const float*)d_in[0];
    const float* Wr  = (const float*)d_in[1];
    const float* br  = (const float*)d_in[2];
    const float* Wn  = (const float*)d_in[3];
    const float* bn  = (const float*)d_in[4];
    const float* eps = (const float*)d_in[5];
    float* out = (float*)d_out;
    (void)n_in;

    const int E    = in_sizes[2];              // 64
    const int D    = in_sizes[1] / E;          // 2048
    const int Ntok = in_sizes[0] / D;          // 32768

    static int configured = 0;                 // idempotent attribute set
    if (!configured) {
        cudaFuncSetAttribute(noisy_topk_router_mma,
                             cudaFuncAttributeMaxDynamicSharedMemorySize, SMEMB);
        configured = 1;
    }

    presplit_w<<<D / 32, 256>>>(Wr, Wn, D);
    noisy_topk_router_mma<<<Ntok / MT, THREADS, SMEMB>>>(
        x, br, bn, eps, out, Ntok, D, (long long)out_size);
}

// round 17
// speedup vs baseline: 1.0327x; 1.0165x over previous
#include <cuda_runtime.h>
#include <math.h>
#include <stdint.h>

// NoisyTopkRouter — TF32x3 split-fp32 via mma.sync.
// R14: 2 CTAs/SM. MT=64 tokens per CTA, 256 threads (8 warps, 2m x 4n,
// warp tile 32x32 = proven R10 inner body). One CTA's MMAs cover the other
// CTA's barrier/cp-wait phases. W pre-split fragment-ordered global (R10),
// W smem ring 2-stage, X smem ring 3-stage.
//
// C[32768 x 128] = X[32768 x 2048] * W^T (W rows 0..63 route, 64..127 noise)
// Epilogue: noisy = logits + eps*softplus(noise); top-2; 2-way softmax scatter.

#define MT      64                        // tokens per CTA
#define THREADS 256
#define SROW    36                        // floats per X smem row
#define XSTG    (MT * SROW * 4)           // 9216 B per X stage
#define NXS     3
#define WSLAB   512                       // W slab stride (bytes)
#define WTILE   16384                     // hi (or lo) W bytes per k-tile
#define WKTB    (2 * WTILE)               // hi+lo = 32768
#define NWS     2
#define WB0     (NXS * XSTG)              // 27648
#define SMEMB   (WB0 + NWS * WKTB)        // 27648 + 65536 = 93184 B
#define NKT     64
#define PADC    130

__device__ unsigned char g_Wpre[NKT * WKTB];   // pre-split W, fragment order

static __device__ __forceinline__ uint32_t f2tf32(float x) {
    uint32_t r;
    asm("cvt.rna.tf32.f32 %0, %1;" : "=r"(r) : "f"(x));
    return r;
}
static __device__ __forceinline__ void split2(float a, uint32_t& hi, uint32_t& lo) {
    hi = f2tf32(a);
    lo = f2tf32(a - __uint_as_float(hi));
}

static __device__ __forceinline__ void mma_tf32(float* d,
                                                uint32_t a0, uint32_t a1,
                                                uint32_t a2, uint32_t a3,
                                                uint32_t b0, uint32_t b1) {
    asm volatile(
        "mma.sync.aligned.m16n8k8.row.col.f32.tf32.tf32.f32 "
        "{%0,%1,%2,%3}, {%4,%5,%6,%7}, {%8,%9}, {%0,%1,%2,%3};"
        : "+f"(d[0]), "+f"(d[1]), "+f"(d[2]), "+f"(d[3])
        : "r"(a0), "r"(a1), "r"(a2), "r"(a3), "r"(b0), "r"(b1));
}

static __device__ __forceinline__ void cp16(uint32_t saddr, const void* gaddr) {
    asm volatile("cp.async.ca.shared.global [%0], [%1], 16;"
                 :: "r"(saddr), "l"(gaddr));
}
static __device__ __forceinline__ uint4 lds128(uint32_t a) {
    uint4 v;
    asm volatile("ld.shared.v4.u32 {%0,%1,%2,%3}, [%4];"
                 : "=r"(v.x), "=r"(v.y), "=r"(v.z), "=r"(v.w) : "r"(a));
    return v;
}

// ---------------- pre-kernel: split W into fragment-ordered slabs ----------
__global__ void presplit_w(const float* __restrict__ Wr,
                           const float* __restrict__ Wn, int D)
{
    const int kt = blockIdx.x;
    for (int idx = threadIdx.x; idx < 4096; idx += 256) {
        const int n  = idx >> 5;
        const int kc = idx & 31;
        const int k  = kt * 32 + kc;
        const float w = (n < 64) ? Wr[(size_t)n * D + k]
                                 : Wn[(size_t)(n - 64) * D + k];
        const uint32_t hi = f2tf32(w);
        const uint32_t lo = f2tf32(w - __uint_as_float(hi));
        const int slab = (n >> 5) * 8 + ((n >> 4) & 1) * 4 + (kc >> 3);
        const int ln   = (n & 7) * 4 + (kc & 3);
        const int r    = ((n >> 3) & 1) * 2 + ((kc >> 2) & 1);
        const int off  = slab * WSLAB + ln * 16 + r * 4;
        *(uint32_t*)(g_Wpre + (size_t)kt * WKTB + off)         = hi;
        *(uint32_t*)(g_Wpre + (size_t)kt * WKTB + WTILE + off) = lo;
    }
}

// ---------------- main kernel ---------------------------------------------
__global__ __launch_bounds__(THREADS, 2)
void noisy_topk_router_mma(const float* __restrict__ x,
                           const float* __restrict__ br,
                           const float* __restrict__ bn,
                           const float* __restrict__ eps,
                           float* __restrict__ out,
                           int Ntok, int D, long long out_size)
{
    extern __shared__ char smem[];
    uint32_t smem_u;
    asm("{ .reg .u64 t; cvta.to.shared.u64 t, %1; cvt.u32.u64 %0, t; }"
        : "=r"(smem_u) : "l"(smem));

    const int tid  = threadIdx.x;
    const int wid  = tid >> 5;      // 0..7
    const int lane = tid & 31;
    const int gid  = lane >> 2;
    const int tig  = lane & 3;
    const int wm   = wid & 1;       // warp m-row (2 x 32 tokens)
    const int wn   = wid >> 1;      // warp n-col (4 x 32 outputs)
    const int m0   = blockIdx.x * MT;

    // X producer: 2 cp16/thread/stage (prow = tid>>2 in 0..63, pqf = (tid&3)*4)
    const int prow = tid >> 2;
    const int pqf  = (tid & 3) * 4;
    const float* xsrc = &x[(size_t)(m0 + prow) * D + pqf];
    const uint32_t pdst = smem_u + prow * (SROW * 4) + pqf * 4;

    // W producer: 8 cp16/thread/stage (linear copy, layout preserved)
    const uint32_t wdst0 = smem_u + WB0 + tid * 16;

    // consumers
    const uint32_t aoff = (uint32_t)((wm * 32 + gid) * SROW + tig) * 4;
    const uint32_t wfb  = smem_u + WB0 + (uint32_t)(wn * 8) * WSLAB + lane * 16;

    float acc[2][4][4];
#pragma unroll
    for (int f = 0; f < 2; ++f)
#pragma unroll
        for (int g = 0; g < 4; ++g)
#pragma unroll
            for (int i = 0; i < 4; ++i) acc[f][g][i] = 0.0f;

    const int nTiles = D / 32;      // 64

    // ---- prologue ----
    // group A: X(0) + W(0); group B: X(1)
    cp16(pdst, xsrc);
    cp16(pdst + 64, xsrc + 16);
    {
        const unsigned char* wsrc = g_Wpre + tid * 16;
#pragma unroll
        for (int q = 0; q < 8; ++q)
            cp16(wdst0 + q * 4096, wsrc + q * 4096);
    }
    asm volatile("cp.async.commit_group;" ::: "memory");
    cp16(pdst + XSTG, xsrc + 32);
    cp16(pdst + XSTG + 64, xsrc + 32 + 16);
    asm volatile("cp.async.commit_group;" ::: "memory");

#pragma unroll 1
    for (int kt = 0; kt < nTiles; ++kt) {
        // issue X(kt+2) and W(kt+1); one mixed commit group per iter
        if (kt + 2 < nTiles) {
            const int xs2 = (kt + 2) % NXS;
            cp16(pdst + xs2 * XSTG, xsrc + (kt + 2) * 32);
            cp16(pdst + xs2 * XSTG + 64, xsrc + (kt + 2) * 32 + 16);
        }
        if (kt + 1 < nTiles) {
            const int ws1 = (kt + 1) & 1;
            const unsigned char* wsrc = g_Wpre + (size_t)(kt + 1) * WKTB + tid * 16;
#pragma unroll
            for (int q = 0; q < 8; ++q)
                cp16(wdst0 + ws1 * WKTB + q * 4096, wsrc + q * 4096);
        }
        asm volatile("cp.async.commit_group;" ::: "memory");
        asm volatile("cp.async.wait_group 1;" ::: "memory");
        __syncthreads();

        const uint32_t aB  = smem_u + (uint32_t)((kt % NXS) * XSTG) + aoff;
        const uint32_t wst = wfb + (uint32_t)((kt & 1) * WKTB);

#pragma unroll
        for (int kcq = 0; kcq < 4; ++kcq) {
            // B fragments: 4 conflict-free LDS.128
            const uint4 Bh0 = lds128(wst + kcq * WSLAB);
            const uint4 Bh1 = lds128(wst + (4 + kcq) * WSLAB);
            const uint4 Bl0 = lds128(wst + WTILE + kcq * WSLAB);
            const uint4 Bl1 = lds128(wst + WTILE + (4 + kcq) * WSLAB);

            // A fragments: 8 LDS.32 + split at consume
            uint32_t Ah[2][4], Al[2][4];
#pragma unroll
            for (int f = 0; f < 2; ++f) {
                const uint32_t qa = aB + (f * 16 * SROW + kcq * 8) * 4;
                float v0, v1, v2, v3;
                asm volatile("ld.shared.f32 %0, [%1];" : "=f"(v0) : "r"(qa));
                asm volatile("ld.shared.f32 %0, [%1];" : "=f"(v1) : "r"(qa + 8 * SROW * 4));
                asm volatile("ld.shared.f32 %0, [%1];" : "=f"(v2) : "r"(qa + 16));
                asm volatile("ld.shared.f32 %0, [%1];" : "=f"(v3) : "r"(qa + 8 * SROW * 4 + 16));
                split2(v0, Ah[f][0], Al[f][0]);
                split2(v1, Ah[f][1], Al[f][1]);
                split2(v2, Ah[f][2], Al[f][2]);
                split2(v3, Ah[f][3], Al[f][3]);
            }

            // pass hi*hi
#pragma unroll
            for (int f = 0; f < 2; ++f) {
                mma_tf32(acc[f][0], Ah[f][0], Ah[f][1], Ah[f][2], Ah[f][3], Bh0.x, Bh0.y);
                mma_tf32(acc[f][1], Ah[f][0], Ah[f][1], Ah[f][2], Ah[f][3], Bh0.z, Bh0.w);
                mma_tf32(acc[f][2], Ah[f][0], Ah[f][1], Ah[f][2], Ah[f][3], Bh1.x, Bh1.y);
                mma_tf32(acc[f][3], Ah[f][0], Ah[f][1], Ah[f][2], Ah[f][3], Bh1.z, Bh1.w);
            }
            // pass hi*lo
#pragma unroll
            for (int f = 0; f < 2; ++f) {
                mma_tf32(acc[f][0], Ah[f][0], Ah[f][1], Ah[f][2], Ah[f][3], Bl0.x, Bl0.y);
                mma_tf32(acc[f][1], Ah[f][0], Ah[f][1], Ah[f][2], Ah[f][3], Bl0.z, Bl0.w);
                mma_tf32(acc[f][2], Ah[f][0], Ah[f][1], Ah[f][2], Ah[f][3], Bl1.x, Bl1.y);
                mma_tf32(acc[f][3], Ah[f][0], Ah[f][1], Ah[f][2], Ah[f][3], Bl1.z, Bl1.w);
            }
            // pass lo*hi
#pragma unroll
            for (int f = 0; f < 2; ++f) {
                mma_tf32(acc[f][0], Al[f][0], Al[f][1], Al[f][2], Al[f][3], Bh0.x, Bh0.y);
                mma_tf32(acc[f][1], Al[f][0], Al[f][1], Al[f][2], Al[f][3], Bh0.z, Bh0.w);
                mma_tf32(acc[f][2], Al[f][0], Al[f][1], Al[f][2], Al[f][3], Bh1.x, Bh1.y);
                mma_tf32(acc[f][3], Al[f][0], Al[f][1], Al[f][2], Al[f][3], Bh1.z, Bh1.w);
            }
        }
        __syncthreads();
    }

    // ---- stage accumulators to smem ----
    float* Cs = reinterpret_cast<float*>(smem);
#pragma unroll
    for (int f = 0; f < 2; ++f)
#pragma unroll
        for (int g = 0; g < 4; ++g) {
            const int row = wm * 32 + f * 16 + gid;
            const int col = wn * 32 + g * 8 + 2 * tig;
            *reinterpret_cast<float2*>(&Cs[row * PADC + col]) =
                make_float2(acc[f][g][0], acc[f][g][1]);
            *reinterpret_cast<float2*>(&Cs[(row + 8) * PADC + col]) =
                make_float2(acc[f][g][2], acc[f][g][3]);
        }
    __syncthreads();

    // ---- epilogue: one thread per token ----
    if (tid < MT) {
        const int tok = m0 + tid;
        const float* crow = &Cs[tid * PADC];

        float v1 = -INFINITY, v2 = -INFINITY;
        int   i1 = -1, i2 = -1;
#pragma unroll 8
        for (int e = 0; e < 64; ++e) {
            const float lg = crow[e]      + __ldg(&br[e]);
            const float ns = crow[64 + e] + __ldg(&bn[e]);
            const float sp = fmaxf(ns, 0.0f) + log1pf(expf(-fabsf(ns)));
            const float nv = lg + __ldg(&eps[(size_t)tok * 64 + e]) * sp;
            if (nv > v1)      { v2 = v1; i2 = i1; v1 = nv; i1 = e; }
            else if (nv > v2) { v2 = nv; i2 = e; }
        }

        const float ed = expf(v2 - v1);
        const float s  = 1.0f + ed;
        const float p1 = 1.0f / s;
        const float p2 = ed / s;

        float* orow = out + (size_t)tok * 64;
#pragma unroll
        for (int e4 = 0; e4 < 64; e4 += 4) {
            float vv[4] = {0.0f, 0.0f, 0.0f, 0.0f};
            if (i1 >= e4 && i1 < e4 + 4) vv[i1 - e4] = p1;
            if (i2 >= e4 && i2 < e4 + 4) vv[i2 - e4] = p2;
            *reinterpret_cast<float4*>(orow + e4) =
                make_float4(vv[0], vv[1], vv[2], vv[3]);
        }

        const long long ibase = (long long)Ntok * 64;
        if (out_size >= ibase + (long long)Ntok * 2) {
            out[ibase + (long long)tok * 2 + 0] = (float)i1;
            out[ibase + (long long)tok * 2 + 1] = (float)i2;
        }
    }
}

extern "C" void kernel_launch(void* const* d_in, const int* in_sizes, int n_in,
                              void* d_out, int out_size)
{
    const float* x   = (const float*)d_in[0];
    const float* Wr  = (const float*)d_in[1];
    const float* br  = (const float*)d_in[2];
    const float* Wn  = (const float*)d_in[3];
    const float* bn  = (const float*)d_in[4];
    const float* eps = (const float*)d_in[5];
    float* out = (float*)d_out;
    (void)n_in;

    const int E    = in_sizes[2];              // 64
    const int D    = in_sizes[1] / E;          // 2048
    const int Ntok = in_sizes[0] / D;          // 32768

    static int configured = 0;                 // idempotent attribute set
    if (!configured) {
        cudaFuncSetAttribute(noisy_topk_router_mma,
                             cudaFuncAttributeMaxDynamicSharedMemorySize, SMEMB);
        configured = 1;
    }

    presplit_w<<<D / 32, 256>>>(Wr, Wn, D);
    noisy_topk_router_mma<<<Ntok / MT, THREADS, SMEMB>>>(
        x, br, bn, eps, out, Ntok, D, (long long)out_size);
}